// round 16
// baseline (speedup 1.0000x reference)
#include <cuda_runtime.h>
#include <cuda_fp16.h>
#include <cstdint>
#include <math.h>

#define EDGES   262144
#define NODES   50000
#define EMB     512
#define FF      1024
#define NGR     64

__device__ __half g_xh[(size_t)(NODES + EDGES) * EMB];  // x in fp16
__device__ __half g_WnT[4096 * 512];   // node weights n-major: [Esrc|Fsrc|Edst|Fdst]
__device__ __half g_WeT[2048 * 512];   // edge-token weights n-major: [Eedge|Fedge]
__device__ __half g_P[(size_t)NODES * 4096];  // node contributions, 64-col groups permuted

__device__ __forceinline__ float gelu_tanh(float x) {
    float inner = fmaf(0.044715f * x * x, x, x);
    float u = 0.7978845608028654f * inner;
    float t; asm("tanh.approx.f32 %0, %1;" : "=f"(t) : "f"(u));
    return 0.5f * x * (1.0f + t);
}
__device__ __forceinline__ void cp16(uint32_t dst, const void* src) {
    asm volatile("cp.async.cg.shared.global [%0], [%1], 16;" :: "r"(dst), "l"(src));
}
#define CP_COMMIT() asm volatile("cp.async.commit_group;" ::: "memory")
#define CP_WAIT1()  asm volatile("cp.async.wait_group 1;" ::: "memory")

__device__ __forceinline__ uint32_t smem_u32(const void* p) {
    uint32_t a;
    asm("{ .reg .u64 t; cvta.to.shared.u64 t, %1; cvt.u32.u64 %0, t; }" : "=r"(a) : "l"(p));
    return a;
}
__device__ __forceinline__ void mma16(float* d, uint32_t a0, uint32_t a1, uint32_t a2,
                                      uint32_t a3, uint32_t b0, uint32_t b1) {
    asm volatile(
        "mma.sync.aligned.m16n8k16.row.col.f32.f16.f16.f32 "
        "{%0,%1,%2,%3},{%4,%5,%6,%7},{%8,%9},{%0,%1,%2,%3};"
        : "+f"(d[0]), "+f"(d[1]), "+f"(d[2]), "+f"(d[3])
        : "r"(a0), "r"(a1), "r"(a2), "r"(a3), "r"(b0), "r"(b1));
}
__device__ __forceinline__ void mma16h(uint32_t* d, uint32_t a0, uint32_t a1, uint32_t a2,
                                       uint32_t a3, uint32_t b0, uint32_t b1) {
    asm volatile(
        "mma.sync.aligned.m16n8k16.row.col.f16.f16.f16.f16 "
        "{%0,%1},{%2,%3,%4,%5},{%6,%7},{%0,%1};"
        : "+r"(d[0]), "+r"(d[1])
        : "r"(a0), "r"(a1), "r"(a2), "r"(a3), "r"(b0), "r"(b1));
}
__device__ __forceinline__ void ldsm4(uint32_t* r, uint32_t addr) {
    asm volatile("ldmatrix.sync.aligned.m8n8.x4.shared.b16 {%0,%1,%2,%3}, [%4];"
        : "=r"(r[0]), "=r"(r[1]), "=r"(r[2]), "=r"(r[3]) : "r"(addr));
}

// ---------------- prep_node: node-x -> fp16 + W1 transpose + out zeroing ----------------

#define NCVT_N4     ((size_t)NODES * EMB / 4)            // 6,400,000 float4s
#define NCVT_BLOCKS ((int)((NCVT_N4 + 255) / 256))       // 25,000
#define TRANS_BLOCKS (16 * 192)                          // 3,072

__global__ void prep_node(const float* __restrict__ x,
                          const float* __restrict__ W1e, const float* __restrict__ W1f,
                          float* __restrict__ out, int out_n) {
    __shared__ float t[32][33];
    const int bid = blockIdx.x;
    const int tid = threadIdx.x;

    if (bid < NCVT_BLOCKS) {
        size_t i = (size_t)bid * 256 + tid;
        if (i < NCVT_N4) {
            float4 f = ((const float4*)x)[i];
            __half2 h0 = __float22half2_rn(make_float2(f.x, f.y));
            __half2 h1 = __float22half2_rn(make_float2(f.z, f.w));
            ((uint2*)g_xh)[i] = make_uint2(*(uint32_t*)&h0, *(uint32_t*)&h1);
        }
        return;
    }

    const int pidx = bid - NCVT_BLOCKS;         // 0..3071
    const int k0 = (pidx & 15) * 32;            // 16 k-blocks
    const int n0 = (pidx >> 4) * 32;            // 192 n-blocks
    const int tx = tid & 31, ty0 = tid >> 5;
    const int gid = pidx * 256 + tid;
    if (gid < out_n) out[gid] = 0.0f;

    const int nblk = n0 >> 10;                  // 0:Esrc 1:Fsrc 2:Edst 3:Fdst 4:Eedge 5:Fedge
    const float* W = (nblk & 1) ? W1f : W1e;
    const int krow = (nblk >> 1) * 512;
    const int ncol = n0 & 1023;
    #pragma unroll
    for (int r = 0; r < 4; r++) {
        int ty = ty0 + r * 8;
        t[ty][tx] = W[(size_t)(krow + k0 + ty) * FF + ncol + tx];
    }
    __syncthreads();
    #pragma unroll
    for (int r = 0; r < 4; r++) {
        int ty = ty0 + r * 8;
        __half v = __float2half_rn(t[tx][ty]);
        int n = n0 + ty, k = k0 + tx;
        if (n < 4096) g_WnT[(size_t)n * 512 + k] = v;
        else          g_WeT[(size_t)(n - 4096) * 512 + k] = v;
    }
}

// ---------------- node GEMM + interleaved edge-token cvt ----------------
// P columns within each 64-aligned group written PERMUTED:
//   orig o = nf*8 + 2*lc + j  ->  o' = lc*16 + nf*2 + j
// so the fused_edge epilogue reads 16 contiguous halfs per lane (2x LDG.128).

#define NG_STA 16384
#define NG_ST  32768
#define GEMM_MX 391                   // ceil(50000/128)
#define GEMM_BLOCKS (GEMM_MX * 32)    // 12,512
#define ECVT_BLOCKS 4096
#define ECVT_PER_BLK 8192             // float4s per cvt block (256 thr x 32)

__global__ __launch_bounds__(256, 2) void node_gemm(const float* __restrict__ x) {
    extern __shared__ char sm[];
    const int bid = blockIdx.x;
    const int tid = threadIdx.x;

    int gemm_id;
    if (bid < 16384) {
        if ((bid & 3) == 3) {
            const int cvt_id = bid >> 2;
            size_t base = NCVT_N4 + (size_t)cvt_id * ECVT_PER_BLK;
            #pragma unroll 4
            for (int j = 0; j < 32; j++) {
                size_t i = base + (size_t)j * 256 + tid;
                float4 f = ((const float4*)x)[i];
                __half2 h0 = __float22half2_rn(make_float2(f.x, f.y));
                __half2 h1 = __float22half2_rn(make_float2(f.z, f.w));
                ((uint2*)g_xh)[i] = make_uint2(*(uint32_t*)&h0, *(uint32_t*)&h1);
            }
            return;
        }
        gemm_id = bid - (bid >> 2);
    } else {
        gemm_id = bid - ECVT_BLOCKS;
    }

    const int wid = tid >> 5, lane = tid & 31;
    const int m0 = (gemm_id % GEMM_MX) * 128;
    const int n0 = (gemm_id / GEMM_MX) * 128;
    const uint32_t sb = smem_u32(sm);

    auto issue = [&](int kt) {
        const uint32_t st = sb + (uint32_t)(kt % 3) * NG_ST;
        const int ko = kt * 64;
        #pragma unroll
        for (int j = 0; j < 4; j++) {
            const int cid = j * 256 + tid;
            const int row = cid >> 3, q = cid & 7;
            int grow = m0 + row; if (grow >= NODES) grow = 0;
            cp16(st + (uint32_t)row * 128 + (uint32_t)((q ^ (row & 7)) << 4),
                 g_xh + (size_t)grow * 512 + ko + q * 8);
        }
        #pragma unroll
        for (int j = 0; j < 4; j++) {
            const int cid = j * 256 + tid;
            const int row = cid >> 3, q = cid & 7;
            cp16(st + NG_STA + (uint32_t)row * 128 + (uint32_t)((q ^ (row & 7)) << 4),
                 g_WnT + (size_t)(n0 + row) * 512 + ko + q * 8);
        }
        CP_COMMIT();
    };
    issue(0); issue(1);

    const int warp_m = wid & 1, warp_n = wid >> 1;
    const int lq = lane >> 2, lc = lane & 3;
    const int arow = warp_m * 64 + (lane & 7) + ((lane >> 3) & 1) * 8;
    const int acs  = (lane >> 4) & 1;
    const int aswz = arow & 7;
    const int brow = warp_n * 32 + ((lane >> 4) & 1) * 8 + (lane & 7);
    const int bcs  = (lane >> 3) & 1;
    const int bswz = brow & 7;

    float acc[4][4][4];
    #pragma unroll
    for (int i = 0; i < 4; i++)
        #pragma unroll
        for (int j = 0; j < 4; j++)
            #pragma unroll
            for (int k = 0; k < 4; k++) acc[i][j][k] = 0.0f;

    for (int kt = 0; kt < 8; kt++) {
        CP_WAIT1();
        __syncthreads();
        if (kt + 2 < 8) issue(kt + 2);
        const uint32_t Ab = sb + (uint32_t)(kt % 3) * NG_ST;
        const uint32_t Bb = Ab + NG_STA;
        #pragma unroll
        for (int c = 0; c < 4; c++) {
            uint32_t a[4][4], b[4][2];
            #pragma unroll
            for (int mf = 0; mf < 4; mf++)
                ldsm4(a[mf], Ab + (uint32_t)(arow + 16 * mf) * 128 +
                             (uint32_t)(((2 * c + acs) ^ aswz) << 4));
            #pragma unroll
            for (int p = 0; p < 2; p++) {
                uint32_t r[4];
                ldsm4(r, Bb + (uint32_t)(brow + 16 * p) * 128 +
                         (uint32_t)(((2 * c + bcs) ^ bswz) << 4));
                b[2 * p][0] = r[0]; b[2 * p][1] = r[1];
                b[2 * p + 1][0] = r[2]; b[2 * p + 1][1] = r[3];
            }
            #pragma unroll
            for (int nf = 0; nf < 4; nf++)
                #pragma unroll
                for (int mf = 0; mf < 4; mf++)
                    mma16(acc[mf][nf], a[mf][0], a[mf][1], a[mf][2], a[mf][3],
                          b[nf][0], b[nf][1]);
        }
    }

    #pragma unroll
    for (int mf = 0; mf < 4; mf++) {
        const int r = m0 + warp_m * 64 + mf * 16 + lq;
        #pragma unroll
        for (int nf = 0; nf < 4; nf++) {
            const int c = n0 + warp_n * 32 + nf * 8 + 2 * lc;
            const int o = c & 63;
            const int cp = (c & ~63) | (((o >> 1) & 3) * 16) | ((o >> 3) << 1);
            if (r < NODES) {
                __half2 h = __float22half2_rn(make_float2(acc[mf][nf][0], acc[mf][nf][1]));
                *(__half2*)&g_P[(size_t)r * 4096 + cp] = h;
            }
            if (r + 8 < NODES) {
                __half2 h = __float22half2_rn(make_float2(acc[mf][nf][2], acc[mf][nf][3]));
                *(__half2*)&g_P[(size_t)(r + 8) * 4096 + cp] = h;
            }
        }
    }
}

// ---------------- fused edge kernel: 2 CTAs/SM, 64x64 tiles, fp16 acc, 2-slot ring ----------------
// Epilogue now gathers P as 2x LDG.128 per (row, side) thanks to the permuted layout.

#define FE_STA 16384
#define FE_ST  49152

__global__ __launch_bounds__(256, 2) void fused_edge(
    const float* __restrict__ pos,
    const float* __restrict__ b1e, const float* __restrict__ W2e, const float* __restrict__ b2e,
    const float* __restrict__ b1f, const float* __restrict__ W2f, const float* __restrict__ b2f,
    const int* __restrict__ batch, const int* __restrict__ edge_index,
    float* __restrict__ out)
{
    extern __shared__ char sm[];
    __shared__ int s_src[128], s_dst[128];
    __shared__ float s_accE[128], s_accF[128], s_energy[NGR];

    const int tid = threadIdx.x, wid = tid >> 5, lane = tid & 31;
    const int e0 = blockIdx.x * 128;
    const uint32_t sb = smem_u32(sm);

    if (tid < 128) {
        s_src[tid] = edge_index[e0 + tid];
        s_dst[tid] = edge_index[EDGES + e0 + tid];
        s_accE[tid] = 0.0f; s_accF[tid] = 0.0f;
    }
    if (tid < NGR) s_energy[tid] = 0.0f;
    __syncthreads();

    auto issueAB = [&](int g) {
        const uint32_t st = sb + (uint32_t)(g & 1) * FE_ST;
        const int kt = g & 7, pass = g >> 3;
        #pragma unroll
        for (int j = 0; j < 4; j++) {          // A: 128 edge-token rows x 8 chunks
            const int cid = j * 256 + tid;
            const int row = cid >> 3, q = cid & 7;
            cp16(st + (uint32_t)row * 128 + (uint32_t)((q ^ (row & 7)) << 4),
                 g_xh + ((size_t)(NODES + e0 + row)) * 512 + kt * 64 + q * 8);
        }
        #pragma unroll
        for (int j = 0; j < 8; j++) {          // B: 256 WeT rows x 8 chunks
            const int cid = j * 256 + tid;
            const int row = cid >> 3, q = cid & 7;
            cp16(st + FE_STA + (uint32_t)row * 128 + (uint32_t)((q ^ (row & 7)) << 4),
                 g_WeT + (size_t)(pass * 256 + row) * 512 + kt * 64 + q * 8);
        }
        CP_COMMIT();
    };
    issueAB(0); issueAB(1);

    const int warp_m = wid & 1, warp_n = wid >> 1;   // tile 64(M) x 64(N)
    const int lq = lane >> 2, lc = lane & 3;
    const int arow = warp_m * 64 + (lane & 7) + ((lane >> 3) & 1) * 8;
    const int acs  = (lane >> 4) & 1;
    const int aswz = arow & 7;
    const int brow = warp_n * 64 + ((lane >> 4) & 1) * 8 + (lane & 7);
    const int bcs  = (lane >> 3) & 1;
    const int bswz = brow & 7;

    uint32_t acch[4][8][2];   // fp16x2 accumulators, persist across the 8 stages of a pass
    #pragma unroll
    for (int i = 0; i < 4; i++)
        #pragma unroll
        for (int j = 0; j < 8; j++) { acch[i][j][0] = 0u; acch[i][j][1] = 0u; }

    for (int g = 0; g < 64; g++) {
        // pending {g, g+1} -> wait_group 1 completes stage g
        CP_WAIT1();
        __syncthreads();

        const uint32_t Ab = sb + (uint32_t)(g & 1) * FE_ST;
        const uint32_t Bb = Ab + FE_STA;

        #pragma unroll
        for (int c = 0; c < 4; c++) {
            uint32_t a[4][4], b[8][2];
            #pragma unroll
            for (int mf = 0; mf < 4; mf++)
                ldsm4(a[mf], Ab + (uint32_t)(arow + 16 * mf) * 128 +
                             (uint32_t)(((2 * c + acs) ^ aswz) << 4));
            #pragma unroll
            for (int p = 0; p < 4; p++) {
                uint32_t r[4];
                ldsm4(r, Bb + (uint32_t)(brow + 16 * p) * 128 +
                         (uint32_t)(((2 * c + bcs) ^ bswz) << 4));
                b[2 * p][0] = r[0]; b[2 * p][1] = r[1];
                b[2 * p + 1][0] = r[2]; b[2 * p + 1][1] = r[3];
            }
            #pragma unroll
            for (int nf = 0; nf < 8; nf++)
                #pragma unroll
                for (int mf = 0; mf < 4; mf++)
                    mma16h(acch[mf][nf], a[mf][0], a[mf][1], a[mf][2], a[mf][3],
                           b[nf][0], b[nf][1]);
        }

        // ---- end-of-pass: vectorized P gather + bias + gelu + dot W2 ----
        if ((g & 7) == 7) {
            const int pass = g >> 3;
            const bool isE = (pass < 4);
            const float* b1 = isE ? b1e : b1f;
            const float* w2 = isE ? W2e : W2f;
            float* sacc = isE ? s_accE : s_accF;
            const int cb = (pass & 3) * 256 + warp_n * 64;
            const int pS = (isE ? 0 : 1024) + cb;
            const int pD = (isE ? 2048 : 3072) + cb;
            #pragma unroll
            for (int mf = 0; mf < 4; mf++) {
                const int r0r = warp_m * 64 + mf * 16 + lq;
                float sv[2];
                #pragma unroll
                for (int h = 0; h < 2; h++) {
                    const int r = r0r + h * 8;
                    // permuted layout: this lane's 16 halfs are contiguous at +lc*16
                    const __half* ps = g_P + (size_t)s_src[r] * 4096 + pS + lc * 16;
                    const __half* pd = g_P + (size_t)s_dst[r] * 4096 + pD + lc * 16;
                    uint32_t S[8], D[8];
                    *(uint4*)&S[0] = *(const uint4*)ps;
                    *(uint4*)&S[4] = *(const uint4*)(ps + 8);
                    *(uint4*)&D[0] = *(const uint4*)pd;
                    *(uint4*)&D[4] = *(const uint4*)(pd + 8);
                    float s = 0.0f;
                    #pragma unroll
                    for (int nf = 0; nf < 8; nf++) {
                        const int cc = nf * 8 + 2 * lc;
                        const float2 bb = *(const float2*)&b1[cb + cc];
                        const float2 ww = *(const float2*)&w2[cb + cc];
                        const float2 pp = __half22float2(*(const __half2*)&S[nf]);
                        const float2 qq = __half22float2(*(const __half2*)&D[nf]);
                        const float2 hh = __half22float2(*(const __half2*)&acch[mf][nf][h]);
                        s = fmaf(gelu_tanh(hh.x + pp.x + qq.x + bb.x), ww.x, s);
                        s = fmaf(gelu_tanh(hh.y + pp.y + qq.y + bb.y), ww.y, s);
                    }
                    sv[h] = s;
                }
                #pragma unroll
                for (int nf = 0; nf < 8; nf++) { acch[mf][nf][0] = 0u; acch[mf][nf][1] = 0u; }
                sv[0] += __shfl_xor_sync(0xffffffffu, sv[0], 1);
                sv[0] += __shfl_xor_sync(0xffffffffu, sv[0], 2);
                sv[1] += __shfl_xor_sync(0xffffffffu, sv[1], 1);
                sv[1] += __shfl_xor_sync(0xffffffffu, sv[1], 2);
                if (lc == 0) {
                    atomicAdd(&sacc[r0r], sv[0]);
                    atomicAdd(&sacc[r0r + 8], sv[1]);
                }
            }
        }

        // all warps done reading slot (g&1) -> safe to refill with stage g+2
        __syncthreads();
        if (g + 2 < 64) issueAB(g + 2);
    }

    __syncthreads();

    if (tid < 128) {
        const int sN = s_src[tid], dN = s_dst[tid];
        const float Ev = s_accE[tid] + b2e[0];
        const float Fv = s_accF[tid] + b2f[0];
        const float vx = pos[3 * sN + 0] - pos[3 * dN + 0];
        const float vy = pos[3 * sN + 1] - pos[3 * dN + 1];
        const float vz = pos[3 * sN + 2] - pos[3 * dN + 2];
        const float n  = sqrtf(vx * vx + vy * vy + vz * vz);
        const float inv = 1.0f / fmaxf(n, 1e-12f);
        atomicAdd(&s_energy[batch[sN]], Ev);
        float* outF = out + NGR;
        atomicAdd(&outF[3 * sN + 0], Fv * vx * inv);
        atomicAdd(&outF[3 * sN + 1], Fv * vy * inv);
        atomicAdd(&outF[3 * sN + 2], Fv * vz * inv);
    }
    __syncthreads();
    if (tid < NGR) atomicAdd(&out[tid], s_energy[tid]);
}

extern "C" void kernel_launch(void* const* d_in, const int* in_sizes, int n_in,
                              void* d_out, int out_size) {
    const float* x    = (const float*)d_in[0];
    const float* pos  = (const float*)d_in[1];
    const float* W1e  = (const float*)d_in[2];
    const float* b1e  = (const float*)d_in[3];
    const float* W2e  = (const float*)d_in[4];
    const float* b2e  = (const float*)d_in[5];
    const float* W1f  = (const float*)d_in[6];
    const float* b1f  = (const float*)d_in[7];
    const float* W2f  = (const float*)d_in[8];
    const float* b2f  = (const float*)d_in[9];
    const int* batch  = (const int*)d_in[10];
    const int* eidx   = (const int*)d_in[11];
    float* out = (float*)d_out;

    // launch 1: node-x cvt + W1 transpose + out zeroing (~29 us)
    prep_node<<<NCVT_BLOCKS + TRANS_BLOCKS, 256>>>(x, W1e, W1f, out, out_size);

    // launch 2: node GEMM (permuted P write) with interleaved edge-token cvt
    const int ng_smem = 3 * NG_ST;  // 96 KB/CTA -> 2 CTAs/SM
    cudaFuncSetAttribute(node_gemm, cudaFuncAttributeMaxDynamicSharedMemorySize, ng_smem);
    node_gemm<<<GEMM_BLOCKS + ECVT_BLOCKS, 256, ng_smem>>>(x);

    // launch 3: fused edge kernel with vectorized P gather
    const int fe_smem = 2 * FE_ST;  // 96 KB/CTA -> 2 CTAs/SM
    cudaFuncSetAttribute(fused_edge, cudaFuncAttributeMaxDynamicSharedMemorySize, fe_smem);
    fused_edge<<<EDGES / 128, 256, fe_smem>>>(
        pos, b1e, W2e, b2e, b1f, W2f, b2f, batch, eidx, out);
}

// round 17
// speedup vs baseline: 1.0094x; 1.0094x over previous
#include <cuda_runtime.h>
#include <cuda_fp16.h>
#include <cstdint>
#include <math.h>

#define EDGES   262144
#define NODES   50000
#define EMB     512
#define FF      1024
#define NGR     64

__device__ __half g_xh[(size_t)(NODES + EDGES) * EMB];  // x in fp16
__device__ __half g_WnT[4096 * 512];   // node weights n-major: [Esrc|Fsrc|Edst|Fdst]
__device__ __half g_WeT[2048 * 512];   // edge-token weights n-major: [Eedge|Fedge]
__device__ __half g_P[(size_t)NODES * 4096];  // node contributions, 64-col groups permuted

__device__ __forceinline__ float gelu_tanh(float x) {
    float inner = fmaf(0.044715f * x * x, x, x);
    float u = 0.7978845608028654f * inner;
    float t; asm("tanh.approx.f32 %0, %1;" : "=f"(t) : "f"(u));
    return 0.5f * x * (1.0f + t);
}
__device__ __forceinline__ void cp16(uint32_t dst, const void* src) {
    asm volatile("cp.async.cg.shared.global [%0], [%1], 16;" :: "r"(dst), "l"(src));
}
__device__ __forceinline__ void prefetchL2(const void* p) {
    asm volatile("prefetch.global.L2 [%0];" :: "l"(p));
}
#define CP_COMMIT() asm volatile("cp.async.commit_group;" ::: "memory")
#define CP_WAIT1()  asm volatile("cp.async.wait_group 1;" ::: "memory")

__device__ __forceinline__ uint32_t smem_u32(const void* p) {
    uint32_t a;
    asm("{ .reg .u64 t; cvta.to.shared.u64 t, %1; cvt.u32.u64 %0, t; }" : "=r"(a) : "l"(p));
    return a;
}
__device__ __forceinline__ void mma16(float* d, uint32_t a0, uint32_t a1, uint32_t a2,
                                      uint32_t a3, uint32_t b0, uint32_t b1) {
    asm volatile(
        "mma.sync.aligned.m16n8k16.row.col.f32.f16.f16.f32 "
        "{%0,%1,%2,%3},{%4,%5,%6,%7},{%8,%9},{%0,%1,%2,%3};"
        : "+f"(d[0]), "+f"(d[1]), "+f"(d[2]), "+f"(d[3])
        : "r"(a0), "r"(a1), "r"(a2), "r"(a3), "r"(b0), "r"(b1));
}
__device__ __forceinline__ void mma16h(uint32_t* d, uint32_t a0, uint32_t a1, uint32_t a2,
                                       uint32_t a3, uint32_t b0, uint32_t b1) {
    asm volatile(
        "mma.sync.aligned.m16n8k16.row.col.f16.f16.f16.f16 "
        "{%0,%1},{%2,%3,%4,%5},{%6,%7},{%0,%1};"
        : "+r"(d[0]), "+r"(d[1])
        : "r"(a0), "r"(a1), "r"(a2), "r"(a3), "r"(b0), "r"(b1));
}
__device__ __forceinline__ void ldsm4(uint32_t* r, uint32_t addr) {
    asm volatile("ldmatrix.sync.aligned.m8n8.x4.shared.b16 {%0,%1,%2,%3}, [%4];"
        : "=r"(r[0]), "=r"(r[1]), "=r"(r[2]), "=r"(r[3]) : "r"(addr));
}

// ---------------- prep_node: node-x -> fp16 + W1 transpose + out zeroing ----------------

#define NCVT_N4     ((size_t)NODES * EMB / 4)            // 6,400,000 float4s
#define NCVT_BLOCKS ((int)((NCVT_N4 + 255) / 256))       // 25,000
#define TRANS_BLOCKS (16 * 192)                          // 3,072

__global__ void prep_node(const float* __restrict__ x,
                          const float* __restrict__ W1e, const float* __restrict__ W1f,
                          float* __restrict__ out, int out_n) {
    __shared__ float t[32][33];
    const int bid = blockIdx.x;
    const int tid = threadIdx.x;

    if (bid < NCVT_BLOCKS) {
        size_t i = (size_t)bid * 256 + tid;
        if (i < NCVT_N4) {
            float4 f = ((const float4*)x)[i];
            __half2 h0 = __float22half2_rn(make_float2(f.x, f.y));
            __half2 h1 = __float22half2_rn(make_float2(f.z, f.w));
            ((uint2*)g_xh)[i] = make_uint2(*(uint32_t*)&h0, *(uint32_t*)&h1);
        }
        return;
    }

    const int pidx = bid - NCVT_BLOCKS;         // 0..3071
    const int k0 = (pidx & 15) * 32;            // 16 k-blocks
    const int n0 = (pidx >> 4) * 32;            // 192 n-blocks
    const int tx = tid & 31, ty0 = tid >> 5;
    const int gid = pidx * 256 + tid;
    if (gid < out_n) out[gid] = 0.0f;

    const int nblk = n0 >> 10;                  // 0:Esrc 1:Fsrc 2:Edst 3:Fdst 4:Eedge 5:Fedge
    const float* W = (nblk & 1) ? W1f : W1e;
    const int krow = (nblk >> 1) * 512;
    const int ncol = n0 & 1023;
    #pragma unroll
    for (int r = 0; r < 4; r++) {
        int ty = ty0 + r * 8;
        t[ty][tx] = W[(size_t)(krow + k0 + ty) * FF + ncol + tx];
    }
    __syncthreads();
    #pragma unroll
    for (int r = 0; r < 4; r++) {
        int ty = ty0 + r * 8;
        __half v = __float2half_rn(t[tx][ty]);
        int n = n0 + ty, k = k0 + tx;
        if (n < 4096) g_WnT[(size_t)n * 512 + k] = v;
        else          g_WeT[(size_t)(n - 4096) * 512 + k] = v;
    }
}

// ---------------- node GEMM + interleaved edge-token cvt ----------------
// P columns within each 64-aligned group written PERMUTED:
//   orig o = nf*8 + 2*lc + j  ->  o' = lc*16 + nf*2 + j

#define NG_STA 16384
#define NG_ST  32768
#define GEMM_MX 391                   // ceil(50000/128)
#define GEMM_BLOCKS (GEMM_MX * 32)    // 12,512
#define ECVT_BLOCKS 4096
#define ECVT_PER_BLK 8192             // float4s per cvt block (256 thr x 32)

__global__ __launch_bounds__(256, 2) void node_gemm(const float* __restrict__ x) {
    extern __shared__ char sm[];
    const int bid = blockIdx.x;
    const int tid = threadIdx.x;

    int gemm_id;
    if (bid < 16384) {
        if ((bid & 3) == 3) {
            const int cvt_id = bid >> 2;
            size_t base = NCVT_N4 + (size_t)cvt_id * ECVT_PER_BLK;
            #pragma unroll 4
            for (int j = 0; j < 32; j++) {
                size_t i = base + (size_t)j * 256 + tid;
                float4 f = ((const float4*)x)[i];
                __half2 h0 = __float22half2_rn(make_float2(f.x, f.y));
                __half2 h1 = __float22half2_rn(make_float2(f.z, f.w));
                ((uint2*)g_xh)[i] = make_uint2(*(uint32_t*)&h0, *(uint32_t*)&h1);
            }
            return;
        }
        gemm_id = bid - (bid >> 2);
    } else {
        gemm_id = bid - ECVT_BLOCKS;
    }

    const int wid = tid >> 5, lane = tid & 31;
    const int m0 = (gemm_id % GEMM_MX) * 128;
    const int n0 = (gemm_id / GEMM_MX) * 128;
    const uint32_t sb = smem_u32(sm);

    auto issue = [&](int kt) {
        const uint32_t st = sb + (uint32_t)(kt % 3) * NG_ST;
        const int ko = kt * 64;
        #pragma unroll
        for (int j = 0; j < 4; j++) {
            const int cid = j * 256 + tid;
            const int row = cid >> 3, q = cid & 7;
            int grow = m0 + row; if (grow >= NODES) grow = 0;
            cp16(st + (uint32_t)row * 128 + (uint32_t)((q ^ (row & 7)) << 4),
                 g_xh + (size_t)grow * 512 + ko + q * 8);
        }
        #pragma unroll
        for (int j = 0; j < 4; j++) {
            const int cid = j * 256 + tid;
            const int row = cid >> 3, q = cid & 7;
            cp16(st + NG_STA + (uint32_t)row * 128 + (uint32_t)((q ^ (row & 7)) << 4),
                 g_WnT + (size_t)(n0 + row) * 512 + ko + q * 8);
        }
        CP_COMMIT();
    };
    issue(0); issue(1);

    const int warp_m = wid & 1, warp_n = wid >> 1;
    const int lq = lane >> 2, lc = lane & 3;
    const int arow = warp_m * 64 + (lane & 7) + ((lane >> 3) & 1) * 8;
    const int acs  = (lane >> 4) & 1;
    const int aswz = arow & 7;
    const int brow = warp_n * 32 + ((lane >> 4) & 1) * 8 + (lane & 7);
    const int bcs  = (lane >> 3) & 1;
    const int bswz = brow & 7;

    float acc[4][4][4];
    #pragma unroll
    for (int i = 0; i < 4; i++)
        #pragma unroll
        for (int j = 0; j < 4; j++)
            #pragma unroll
            for (int k = 0; k < 4; k++) acc[i][j][k] = 0.0f;

    for (int kt = 0; kt < 8; kt++) {
        CP_WAIT1();
        __syncthreads();
        if (kt + 2 < 8) issue(kt + 2);
        const uint32_t Ab = sb + (uint32_t)(kt % 3) * NG_ST;
        const uint32_t Bb = Ab + NG_STA;
        #pragma unroll
        for (int c = 0; c < 4; c++) {
            uint32_t a[4][4], b[4][2];
            #pragma unroll
            for (int mf = 0; mf < 4; mf++)
                ldsm4(a[mf], Ab + (uint32_t)(arow + 16 * mf) * 128 +
                             (uint32_t)(((2 * c + acs) ^ aswz) << 4));
            #pragma unroll
            for (int p = 0; p < 2; p++) {
                uint32_t r[4];
                ldsm4(r, Bb + (uint32_t)(brow + 16 * p) * 128 +
                         (uint32_t)(((2 * c + bcs) ^ bswz) << 4));
                b[2 * p][0] = r[0]; b[2 * p][1] = r[1];
                b[2 * p + 1][0] = r[2]; b[2 * p + 1][1] = r[3];
            }
            #pragma unroll
            for (int nf = 0; nf < 4; nf++)
                #pragma unroll
                for (int mf = 0; mf < 4; mf++)
                    mma16(acc[mf][nf], a[mf][0], a[mf][1], a[mf][2], a[mf][3],
                          b[nf][0], b[nf][1]);
        }
    }

    #pragma unroll
    for (int mf = 0; mf < 4; mf++) {
        const int r = m0 + warp_m * 64 + mf * 16 + lq;
        #pragma unroll
        for (int nf = 0; nf < 4; nf++) {
            const int c = n0 + warp_n * 32 + nf * 8 + 2 * lc;
            const int o = c & 63;
            const int cp = (c & ~63) | (((o >> 1) & 3) * 16) | ((o >> 3) << 1);
            if (r < NODES) {
                __half2 h = __float22half2_rn(make_float2(acc[mf][nf][0], acc[mf][nf][1]));
                *(__half2*)&g_P[(size_t)r * 4096 + cp] = h;
            }
            if (r + 8 < NODES) {
                __half2 h = __float22half2_rn(make_float2(acc[mf][nf][2], acc[mf][nf][3]));
                *(__half2*)&g_P[(size_t)(r + 8) * 4096 + cp] = h;
            }
        }
    }
}

// ---------------- fused edge kernel: 2 CTAs/SM, 64x64 tiles, fp16 acc, 2-slot ring ----------------
// Stage (g&7)==6 prefetches the upcoming epilogue's P rows into L2 (~2 stages of lead).

#define FE_STA 16384
#define FE_ST  49152

__global__ __launch_bounds__(256, 2) void fused_edge(
    const float* __restrict__ pos,
    const float* __restrict__ b1e, const float* __restrict__ W2e, const float* __restrict__ b2e,
    const float* __restrict__ b1f, const float* __restrict__ W2f, const float* __restrict__ b2f,
    const int* __restrict__ batch, const int* __restrict__ edge_index,
    float* __restrict__ out)
{
    extern __shared__ char sm[];
    __shared__ int s_src[128], s_dst[128];
    __shared__ float s_accE[128], s_accF[128], s_energy[NGR];

    const int tid = threadIdx.x, wid = tid >> 5, lane = tid & 31;
    const int e0 = blockIdx.x * 128;
    const uint32_t sb = smem_u32(sm);

    if (tid < 128) {
        s_src[tid] = edge_index[e0 + tid];
        s_dst[tid] = edge_index[EDGES + e0 + tid];
        s_accE[tid] = 0.0f; s_accF[tid] = 0.0f;
    }
    if (tid < NGR) s_energy[tid] = 0.0f;
    __syncthreads();

    auto issueAB = [&](int g) {
        const uint32_t st = sb + (uint32_t)(g & 1) * FE_ST;
        const int kt = g & 7, pass = g >> 3;
        #pragma unroll
        for (int j = 0; j < 4; j++) {          // A: 128 edge-token rows x 8 chunks
            const int cid = j * 256 + tid;
            const int row = cid >> 3, q = cid & 7;
            cp16(st + (uint32_t)row * 128 + (uint32_t)((q ^ (row & 7)) << 4),
                 g_xh + ((size_t)(NODES + e0 + row)) * 512 + kt * 64 + q * 8);
        }
        #pragma unroll
        for (int j = 0; j < 8; j++) {          // B: 256 WeT rows x 8 chunks
            const int cid = j * 256 + tid;
            const int row = cid >> 3, q = cid & 7;
            cp16(st + FE_STA + (uint32_t)row * 128 + (uint32_t)((q ^ (row & 7)) << 4),
                 g_WeT + (size_t)(pass * 256 + row) * 512 + kt * 64 + q * 8);
        }
        CP_COMMIT();
    };
    issueAB(0); issueAB(1);

    const int warp_m = wid & 1, warp_n = wid >> 1;   // tile 64(M) x 64(N)
    const int lq = lane >> 2, lc = lane & 3;
    const int arow = warp_m * 64 + (lane & 7) + ((lane >> 3) & 1) * 8;
    const int acs  = (lane >> 4) & 1;
    const int aswz = arow & 7;
    const int brow = warp_n * 64 + ((lane >> 4) & 1) * 8 + (lane & 7);
    const int bcs  = (lane >> 3) & 1;
    const int bswz = brow & 7;

    uint32_t acch[4][8][2];   // fp16x2 accumulators, persist across the 8 stages of a pass
    #pragma unroll
    for (int i = 0; i < 4; i++)
        #pragma unroll
        for (int j = 0; j < 8; j++) { acch[i][j][0] = 0u; acch[i][j][1] = 0u; }

    for (int g = 0; g < 64; g++) {
        // pending {g, g+1} -> wait_group 1 completes stage g
        CP_WAIT1();
        __syncthreads();

        const uint32_t Ab = sb + (uint32_t)(g & 1) * FE_ST;
        const uint32_t Bb = Ab + FE_STA;

        // ---- stage 6 of each pass: prefetch upcoming epilogue's P rows into L2 ----
        if ((g & 7) == 6) {
            const int pass = g >> 3;
            const bool isE = (pass < 4);
            const int cb = (pass & 3) * 256 + warp_n * 64;
            const int pS = (isE ? 0 : 1024) + cb;
            const int pD = (isE ? 2048 : 3072) + cb;
            #pragma unroll
            for (int mf = 0; mf < 4; mf++) {
                #pragma unroll
                for (int h = 0; h < 2; h++) {
                    const int r = warp_m * 64 + mf * 16 + lq + h * 8;
                    prefetchL2(g_P + (size_t)s_src[r] * 4096 + pS + lc * 16);
                    prefetchL2(g_P + (size_t)s_dst[r] * 4096 + pD + lc * 16);
                }
            }
        }

        #pragma unroll
        for (int c = 0; c < 4; c++) {
            uint32_t a[4][4], b[8][2];
            #pragma unroll
            for (int mf = 0; mf < 4; mf++)
                ldsm4(a[mf], Ab + (uint32_t)(arow + 16 * mf) * 128 +
                             (uint32_t)(((2 * c + acs) ^ aswz) << 4));
            #pragma unroll
            for (int p = 0; p < 4; p++) {
                uint32_t r[4];
                ldsm4(r, Bb + (uint32_t)(brow + 16 * p) * 128 +
                         (uint32_t)(((2 * c + bcs) ^ bswz) << 4));
                b[2 * p][0] = r[0]; b[2 * p][1] = r[1];
                b[2 * p + 1][0] = r[2]; b[2 * p + 1][1] = r[3];
            }
            #pragma unroll
            for (int nf = 0; nf < 8; nf++)
                #pragma unroll
                for (int mf = 0; mf < 4; mf++)
                    mma16h(acch[mf][nf], a[mf][0], a[mf][1], a[mf][2], a[mf][3],
                           b[nf][0], b[nf][1]);
        }

        // ---- end-of-pass: vectorized P gather (L2-warm) + bias + gelu + dot W2 ----
        if ((g & 7) == 7) {
            const int pass = g >> 3;
            const bool isE = (pass < 4);
            const float* b1 = isE ? b1e : b1f;
            const float* w2 = isE ? W2e : W2f;
            float* sacc = isE ? s_accE : s_accF;
            const int cb = (pass & 3) * 256 + warp_n * 64;
            const int pS = (isE ? 0 : 1024) + cb;
            const int pD = (isE ? 2048 : 3072) + cb;
            #pragma unroll
            for (int mf = 0; mf < 4; mf++) {
                const int r0r = warp_m * 64 + mf * 16 + lq;
                float sv[2];
                #pragma unroll
                for (int h = 0; h < 2; h++) {
                    const int r = r0r + h * 8;
                    const __half* ps = g_P + (size_t)s_src[r] * 4096 + pS + lc * 16;
                    const __half* pd = g_P + (size_t)s_dst[r] * 4096 + pD + lc * 16;
                    uint32_t S[8], D[8];
                    *(uint4*)&S[0] = *(const uint4*)ps;
                    *(uint4*)&S[4] = *(const uint4*)(ps + 8);
                    *(uint4*)&D[0] = *(const uint4*)pd;
                    *(uint4*)&D[4] = *(const uint4*)(pd + 8);
                    float s = 0.0f;
                    #pragma unroll
                    for (int nf = 0; nf < 8; nf++) {
                        const int cc = nf * 8 + 2 * lc;
                        const float2 bb = *(const float2*)&b1[cb + cc];
                        const float2 ww = *(const float2*)&w2[cb + cc];
                        const float2 pp = __half22float2(*(const __half2*)&S[nf]);
                        const float2 qq = __half22float2(*(const __half2*)&D[nf]);
                        const float2 hh = __half22float2(*(const __half2*)&acch[mf][nf][h]);
                        s = fmaf(gelu_tanh(hh.x + pp.x + qq.x + bb.x), ww.x, s);
                        s = fmaf(gelu_tanh(hh.y + pp.y + qq.y + bb.y), ww.y, s);
                    }
                    sv[h] = s;
                }
                #pragma unroll
                for (int nf = 0; nf < 8; nf++) { acch[mf][nf][0] = 0u; acch[mf][nf][1] = 0u; }
                sv[0] += __shfl_xor_sync(0xffffffffu, sv[0], 1);
                sv[0] += __shfl_xor_sync(0xffffffffu, sv[0], 2);
                sv[1] += __shfl_xor_sync(0xffffffffu, sv[1], 1);
                sv[1] += __shfl_xor_sync(0xffffffffu, sv[1], 2);
                if (lc == 0) {
                    atomicAdd(&sacc[r0r], sv[0]);
                    atomicAdd(&sacc[r0r + 8], sv[1]);
                }
            }
        }

        // all warps done reading slot (g&1) -> safe to refill with stage g+2
        __syncthreads();
        if (g + 2 < 64) issueAB(g + 2);
    }

    __syncthreads();

    if (tid < 128) {
        const int sN = s_src[tid], dN = s_dst[tid];
        const float Ev = s_accE[tid] + b2e[0];
        const float Fv = s_accF[tid] + b2f[0];
        const float vx = pos[3 * sN + 0] - pos[3 * dN + 0];
        const float vy = pos[3 * sN + 1] - pos[3 * dN + 1];
        const float vz = pos[3 * sN + 2] - pos[3 * dN + 2];
        const float n  = sqrtf(vx * vx + vy * vy + vz * vz);
        const float inv = 1.0f / fmaxf(n, 1e-12f);
        atomicAdd(&s_energy[batch[sN]], Ev);
        float* outF = out + NGR;
        atomicAdd(&outF[3 * sN + 0], Fv * vx * inv);
        atomicAdd(&outF[3 * sN + 1], Fv * vy * inv);
        atomicAdd(&outF[3 * sN + 2], Fv * vz * inv);
    }
    __syncthreads();
    if (tid < NGR) atomicAdd(&out[tid], s_energy[tid]);
}

extern "C" void kernel_launch(void* const* d_in, const int* in_sizes, int n_in,
                              void* d_out, int out_size) {
    const float* x    = (const float*)d_in[0];
    const float* pos  = (const float*)d_in[1];
    const float* W1e  = (const float*)d_in[2];
    const float* b1e  = (const float*)d_in[3];
    const float* W2e  = (const float*)d_in[4];
    const float* b2e  = (const float*)d_in[5];
    const float* W1f  = (const float*)d_in[6];
    const float* b1f  = (const float*)d_in[7];
    const float* W2f  = (const float*)d_in[8];
    const float* b2f  = (const float*)d_in[9];
    const int* batch  = (const int*)d_in[10];
    const int* eidx   = (const int*)d_in[11];
    float* out = (float*)d_out;

    // launch 1: node-x cvt + W1 transpose + out zeroing (~29 us)
    prep_node<<<NCVT_BLOCKS + TRANS_BLOCKS, 256>>>(x, W1e, W1f, out, out_size);

    // launch 2: node GEMM (permuted P write) with interleaved edge-token cvt
    const int ng_smem = 3 * NG_ST;  // 96 KB/CTA -> 2 CTAs/SM
    cudaFuncSetAttribute(node_gemm, cudaFuncAttributeMaxDynamicSharedMemorySize, ng_smem);
    node_gemm<<<GEMM_BLOCKS + ECVT_BLOCKS, 256, ng_smem>>>(x);

    // launch 3: fused edge kernel with L2-prefetched, vectorized P gather
    const int fe_smem = 2 * FE_ST;  // 96 KB/CTA -> 2 CTAs/SM
    cudaFuncSetAttribute(fused_edge, cudaFuncAttributeMaxDynamicSharedMemorySize, fe_smem);
    fused_edge<<<EDGES / 128, 256, fe_smem>>>(
        pos, b1e, W2e, b2e, b1f, W2f, b2f, batch, eidx, out);
}